// round 3
// baseline (speedup 1.0000x reference)
#include <cuda_runtime.h>

#define NCLS   10
#define NTHR   256
#define WARPS  8
#define NBLK   888   // 148 SMs * 6 blocks

__device__ float g_sum[NCLS];
__device__ float g_cnt[NCLS];

__global__ void zero_kernel() {
    int t = threadIdx.x;
    if (t < NCLS) { g_sum[t] = 0.f; g_cnt[t] = 0.f; }
}

__global__ __launch_bounds__(NTHR) void hist_kernel(
    const float4* __restrict__ o4,
    const float4* __restrict__ t4,
    const int4*   __restrict__ m4,
    const float*  __restrict__ o_s,
    const float*  __restrict__ t_s,
    const int*    __restrict__ m_s,
    int n4, int n)
{
    // Per-warp, per-lane-column accumulators: acc[warp][cls][lane] = (sum, cnt).
    // Lane owns its column -> plain RMW, no atomics. Bank index =
    // (cls*64 + lane*2) % 32 = (lane*2) % 32 -> conflict-free per half-warp phase.
    __shared__ float2 acc[WARPS][NCLS][32];

    int tid = threadIdx.x;
    int w = tid >> 5, l = tid & 31;

    #pragma unroll
    for (int c = 0; c < NCLS; ++c) acc[w][c][l] = make_float2(0.f, 0.f);
    __syncthreads();

    float2* lane_base = &acc[w][0][l];   // class stride = 32 float2

    int idx    = blockIdx.x * NTHR + tid;
    int stride = gridDim.x * NTHR;

    for (int i = idx; i < n4; i += stride) {
        float4 o = o4[i];
        float4 t = t4[i];
        int4   m = m4[i];

        {   // elem 0
            float d  = o.x - t.x;
            float mf = (float)m.x;
            int   c  = (int)t.x;
            float dm = d * mf;
            float2 v = lane_base[c * 32];
            v.x = fmaf(d, dm, v.x);
            v.y += mf;
            lane_base[c * 32] = v;
        }
        {   // elem 1
            float d  = o.y - t.y;
            float mf = (float)m.y;
            int   c  = (int)t.y;
            float dm = d * mf;
            float2 v = lane_base[c * 32];
            v.x = fmaf(d, dm, v.x);
            v.y += mf;
            lane_base[c * 32] = v;
        }
        {   // elem 2
            float d  = o.z - t.z;
            float mf = (float)m.z;
            int   c  = (int)t.z;
            float dm = d * mf;
            float2 v = lane_base[c * 32];
            v.x = fmaf(d, dm, v.x);
            v.y += mf;
            lane_base[c * 32] = v;
        }
        {   // elem 3
            float d  = o.w - t.w;
            float mf = (float)m.w;
            int   c  = (int)t.w;
            float dm = d * mf;
            float2 v = lane_base[c * 32];
            v.x = fmaf(d, dm, v.x);
            v.y += mf;
            lane_base[c * 32] = v;
        }
    }

    // Scalar tail (defensive; N = 16.78M is divisible by 4 so normally empty).
    if (blockIdx.x == 0) {
        for (int i = n4 * 4 + tid; i < n; i += NTHR) {
            float d  = o_s[i] - t_s[i];
            float mf = (float)m_s[i];
            int   c  = (int)t_s[i];
            float dm = d * mf;
            float2 v = lane_base[c * 32];
            v.x = fmaf(d, dm, v.x);
            v.y += mf;
            lane_base[c * 32] = v;
        }
    }

    __syncthreads();

    // Block reduction: 320 slots (cls, lane). Consecutive threads cover the
    // lane dimension so the shfl reduction stays within one warp per class.
    for (int s = tid; s < NCLS * 32; s += NTHR) {
        int c = s >> 5, ll = s & 31;
        float sum = 0.f, cnt = 0.f;
        #pragma unroll
        for (int ww = 0; ww < WARPS; ++ww) {
            float2 v = acc[ww][c][ll];
            sum += v.x; cnt += v.y;
        }
        #pragma unroll
        for (int off = 16; off; off >>= 1) {
            sum += __shfl_down_sync(0xffffffffu, sum, off);
            cnt += __shfl_down_sync(0xffffffffu, cnt, off);
        }
        if (ll == 0) {
            atomicAdd(&g_sum[c], sum);
            atomicAdd(&g_cnt[c], cnt);
        }
    }
}

__global__ void finalize_kernel(float* __restrict__ out, int out_size) {
    __shared__ float le[NCLS];
    int t = threadIdx.x;   // 32 threads
    if (t < NCLS) {
        float s = g_sum[t], n = g_cnt[t];
        float v = (n > 0.f) ? s / fmaxf(n, 1.f) : 0.f;
        le[t] = v;
        if (1 + t  < out_size) out[1 + t]  = v;  // loss_each
        if (11 + t < out_size) out[11 + t] = n;  // class_n
    }
    __syncthreads();
    if (t == 0) {
        float loss = 0.f;
        #pragma unroll
        for (int c = 0; c < NCLS; ++c) loss += 0.1f * le[c];
        if (out_size > 0) out[0] = loss;
    }
    // Zero any tail beyond the 21 expected outputs (d_out is poisoned).
    for (int i = 21 + t; i < out_size; i += 32) out[i] = 0.f;
}

extern "C" void kernel_launch(void* const* d_in, const int* in_sizes, int n_in,
                              void* d_out, int out_size) {
    const float* outputs = (const float*)d_in[0];
    const float* targets = (const float*)d_in[1];
    const int*   mask    = (const int*)d_in[2];
    int n  = in_sizes[0];
    int n4 = n >> 2;

    zero_kernel<<<1, 32>>>();
    hist_kernel<<<NBLK, NTHR>>>(
        (const float4*)outputs, (const float4*)targets, (const int4*)mask,
        outputs, targets, mask, n4, n);
    finalize_kernel<<<1, 32>>>((float*)d_out, out_size);
}